// round 5
// baseline (speedup 1.0000x reference)
#include <cuda_runtime.h>
#include <math.h>
#include <float.h>
#include <stdint.h>

#define N       16384
#define DIN     13
#define KNN     8
#define QCTA    64               // queries per CTA (4 warps x m16)
#define CHUNK   128              // j per staged chunk
#define NCHUNK  (N / CHUNK)      // 128
#define NTILE   (CHUNK / 8)      // 16 n8-tiles per chunk
#define NLIST   4                // partial lists per query

// ---- scratch (no allocs allowed) ----
__device__ float  g_x[N * 16];           // embedded points
__device__ float  g_sq[N];               // squared norms
__device__ float  g_a[N * 32];           // [ah(16)|al(16)] of -2*x
__device__ float  g_b[N * 32];           // [bh(16)|bl(16)] of  x
__device__ float4 g_bf[(N / 8) * 64];    // B in mma-fragment order (hi|lo per tile)
__device__ float  g_pd[N * NLIST * KNN]; // partial top-k surrogate distances
__device__ int    g_pi[N * NLIST * KNN];
__device__ int    g_idx[N * KNN];        // final knn indices
__device__ float  g_feats[N * 16];       // mean edge messages

__device__ __forceinline__ float silu_f(float v) {
    return v / (1.0f + expf(-v));
}
__device__ __forceinline__ float silu_fast(float v) {
    return __fdividef(v, 1.0f + __expf(-v));
}
__device__ __forceinline__ float tf32r(float v) {
    uint32_t u; asm("cvt.rna.tf32.f32 %0, %1;" : "=r"(u) : "f"(v));
    return __uint_as_float(u);
}
__device__ __forceinline__ uint32_t smem_u32(const void* p) {
    uint32_t a;
    asm("{ .reg .u64 t; cvta.to.shared.u64 t, %1; cvt.u32.u64 %0, t; }"
        : "=r"(a) : "l"(p));
    return a;
}
__device__ __forceinline__ void cp_async16(uint32_t saddr, const void* g) {
    asm volatile("cp.async.cg.shared.global [%0], [%1], 16;" :: "r"(saddr), "l"(g));
}
#define CP_COMMIT() asm volatile("cp.async.commit_group;" ::: "memory")
#define CP_WAIT0()  asm volatile("cp.async.wait_group 0;" ::: "memory")

// m16n8k8 tf32 mma (PTX sm_80+, valid on compute_103 base target)
__device__ __forceinline__ void mma_tf32(float& c0, float& c1, float& c2, float& c3,
                                         uint32_t a0, uint32_t a1, uint32_t a2, uint32_t a3,
                                         uint32_t b0, uint32_t b1) {
    asm volatile(
        "mma.sync.aligned.m16n8k8.row.col.f32.tf32.tf32.f32 "
        "{%0,%1,%2,%3}, {%4,%5,%6,%7}, {%8,%9}, {%0,%1,%2,%3};"
        : "+f"(c0), "+f"(c1), "+f"(c2), "+f"(c3)
        : "r"(a0), "r"(a1), "r"(a2), "r"(a3), "r"(b0), "r"(b1));
}

// sorted top-8 insertion (strict <, ascending j scan -> lower index wins ties)
__device__ __forceinline__ void upd8(float* td, int* ti, float d, int j) {
    if (d < td[KNN - 1]) {
        td[KNN - 1] = d; ti[KNN - 1] = j;
        #pragma unroll
        for (int s = KNN - 1; s >= 1; --s) {
            if (td[s] < td[s - 1]) {
                float tf = td[s]; td[s] = td[s-1]; td[s-1] = tf;
                int   tn = ti[s]; ti[s] = ti[s-1]; ti[s-1] = tn;
            }
        }
    }
}

// ============================================================
// Kernel 1: per-point MLP -> x, sq, tf32 hi/lo splits
// ============================================================
__global__ void mlp_kernel(const float* __restrict__ xp,
                           const float* __restrict__ W1, const float* __restrict__ b1,
                           const float* __restrict__ W2, const float* __restrict__ b2,
                           const float* __restrict__ W3, const float* __restrict__ b3)
{
    __shared__ float sW1[DIN * 8], sb1[8];
    __shared__ float sW2[8 * 16],  sb2[16];
    __shared__ float sW3[16 * 15], sb3[15];

    int t = threadIdx.x;
    for (int i = t; i < DIN * 8; i += blockDim.x) sW1[i] = W1[i];
    for (int i = t; i < 8;       i += blockDim.x) sb1[i] = b1[i];
    for (int i = t; i < 8 * 16;  i += blockDim.x) sW2[i] = W2[i];
    for (int i = t; i < 16;      i += blockDim.x) sb2[i] = b2[i];
    for (int i = t; i < 16 * 15; i += blockDim.x) sW3[i] = W3[i];
    for (int i = t; i < 15;      i += blockDim.x) sb3[i] = b3[i];
    __syncthreads();

    int i = blockIdx.x * blockDim.x + t;
    if (i >= N) return;

    float in[DIN];
    #pragma unroll
    for (int d = 0; d < DIN; ++d) in[d] = xp[i * DIN + d];

    float h1[8];
    #pragma unroll
    for (int h = 0; h < 8; ++h) {
        float a = sb1[h];
        #pragma unroll
        for (int d = 0; d < DIN; ++d) a = fmaf(in[d], sW1[d * 8 + h], a);
        h1[h] = silu_f(a);
    }
    float h2[16];
    #pragma unroll
    for (int h = 0; h < 16; ++h) {
        float a = sb2[h];
        #pragma unroll
        for (int d = 0; d < 8; ++d) a = fmaf(h1[d], sW2[d * 16 + h], a);
        h2[h] = silu_f(a);
    }
    float xr[16];
    #pragma unroll
    for (int h = 0; h < 15; ++h) {
        float a = sb3[h];
        #pragma unroll
        for (int d = 0; d < 16; ++d) a = fmaf(h2[d], sW3[d * 15 + h], a);
        xr[h] = a;
    }
    xr[15] = in[DIN - 1];

    float s = 0.0f;
    #pragma unroll
    for (int k = 0; k < 16; ++k) s = fmaf(xr[k], xr[k], s);

    #pragma unroll
    for (int k = 0; k < 16; ++k) {
        float v = xr[k];
        g_x[i * 16 + k] = v;
        float a  = -2.0f * v;
        float ah = tf32r(a);
        float al = tf32r(a - ah);
        g_a[i * 32 + k]      = ah;
        g_a[i * 32 + 16 + k] = al;
        float bh = tf32r(v);
        float bl = tf32r(v - bh);
        g_b[i * 32 + k]      = bh;
        g_b[i * 32 + 16 + k] = bl;
    }
    g_sq[i] = s;
}

// ============================================================
// Kernel 1b: reorder B into mma fragment layout
//   tile T = j rows [8T, 8T+8); lane l: row 8T + l/4, cols (l%4)+{0,4,8,12}
// ============================================================
__global__ void bfrag_kernel()
{
    int u = blockIdx.x * 256 + threadIdx.x;        // (T, lane)
    int T = u >> 5, l = u & 31;
    int row = T * 8 + (l >> 2);
    int c   = l & 3;
    const float* b = g_b + row * 32;
    g_bf[T * 64 + l]      = make_float4(b[c],      b[c + 4],      b[c + 8],      b[c + 12]);
    g_bf[T * 64 + 32 + l] = make_float4(b[16 + c], b[16 + c + 4], b[16 + c + 8], b[16 + c + 12]);
}

// ============================================================
// Kernel 2: distance GEMM via mma.sync tf32 (3-term split) + fused top-8
//   CTA: 128 threads (4 warps), 64 queries. Loops all 16384 j.
// ============================================================
__global__ void __launch_bounds__(128) knn_mma_kernel()
{
    __shared__ float4 sBf[2][NTILE * 64];   // 2 x 16KB
    __shared__ float  ssq[2][CHUNK];

    const int t    = threadIdx.x;
    const int lane = t & 31;
    const int w    = t >> 5;
    const int gid  = lane >> 2;     // group id (query row within m16)
    const int t4   = lane & 3;      // thread-in-group
    const int q0   = blockIdx.x * QCTA + w * 16;

    // ---- load persistent A fragments (queries, tf32 hi/lo) ----
    uint32_t ah0[4], ah1[4], al0[4], al1[4];
    {
        const float* A0 = g_a + (size_t)(q0 + gid) * 32;
        const float* A1 = g_a + (size_t)(q0 + gid + 8) * 32;
        ah0[0] = __float_as_uint(A0[t4]);      ah0[1] = __float_as_uint(A1[t4]);
        ah0[2] = __float_as_uint(A0[t4 + 4]);  ah0[3] = __float_as_uint(A1[t4 + 4]);
        ah1[0] = __float_as_uint(A0[t4 + 8]);  ah1[1] = __float_as_uint(A1[t4 + 8]);
        ah1[2] = __float_as_uint(A0[t4 + 12]); ah1[3] = __float_as_uint(A1[t4 + 12]);
        al0[0] = __float_as_uint(A0[16 + t4]);      al0[1] = __float_as_uint(A1[16 + t4]);
        al0[2] = __float_as_uint(A0[16 + t4 + 4]);  al0[3] = __float_as_uint(A1[16 + t4 + 4]);
        al1[0] = __float_as_uint(A0[16 + t4 + 8]);  al1[1] = __float_as_uint(A1[16 + t4 + 8]);
        al1[2] = __float_as_uint(A0[16 + t4 + 12]); al1[3] = __float_as_uint(A1[16 + t4 + 12]);
    }

    float td0[KNN], td1[KNN];
    int   ti0[KNN], ti1[KNN];
    #pragma unroll
    for (int k = 0; k < KNN; ++k) {
        td0[k] = FLT_MAX; ti0[k] = 0x7fffffff;
        td1[k] = FLT_MAX; ti1[k] = 0x7fffffff;
    }

    const uint32_t sB_addr  = smem_u32(sBf);
    const uint32_t ssq_addr = smem_u32(ssq);

    // prefetch chunk 0 into buf 0
    {
        const float4* src = g_bf;
        for (int u = t; u < NTILE * 64; u += 128)
            cp_async16(sB_addr + (uint32_t)u * 16, src + u);
        if (t < CHUNK / 4)
            cp_async16(ssq_addr + (uint32_t)t * 16, (const float4*)g_sq + t);
        CP_COMMIT();
    }

    for (int ch = 0; ch < NCHUNK; ++ch) {
        const int buf = ch & 1;
        CP_WAIT0();
        __syncthreads();

        const int cn = ch + 1;
        if (cn < NCHUNK) {
            const int nb = cn & 1;
            const float4* src = g_bf + (size_t)cn * (NTILE * 64);
            for (int u = t; u < NTILE * 64; u += 128)
                cp_async16(sB_addr + (uint32_t)(nb * NTILE * 64 + u) * 16, src + u);
            if (t < CHUNK / 4)
                cp_async16(ssq_addr + (uint32_t)(nb * CHUNK + t * 4) * 4,
                           (const float4*)(g_sq + cn * CHUNK) + t);
            CP_COMMIT();
        }

        const uint4* btile = (const uint4*)sBf[buf];
        const float* sqv   = ssq[buf];
        const int    jch   = ch * CHUNK;

        #pragma unroll 4
        for (int nt = 0; nt < NTILE; ++nt) {
            uint4 bh = btile[nt * 64 + lane];
            uint4 bl = btile[nt * 64 + 32 + lane];

            float cA0 = 0.f, cA1 = 0.f, cA2 = 0.f, cA3 = 0.f;
            float cB0 = 0.f, cB1 = 0.f, cB2 = 0.f, cB3 = 0.f;
            // hi*hi (k0,k1)
            mma_tf32(cA0, cA1, cA2, cA3, ah0[0], ah0[1], ah0[2], ah0[3], bh.x, bh.y);
            mma_tf32(cB0, cB1, cB2, cB3, al0[0], al0[1], al0[2], al0[3], bh.x, bh.y);
            mma_tf32(cA0, cA1, cA2, cA3, ah1[0], ah1[1], ah1[2], ah1[3], bh.z, bh.w);
            mma_tf32(cB0, cB1, cB2, cB3, al1[0], al1[1], al1[2], al1[3], bh.z, bh.w);
            // hi*lo (k0,k1)
            mma_tf32(cA0, cA1, cA2, cA3, ah0[0], ah0[1], ah0[2], ah0[3], bl.x, bl.y);
            mma_tf32(cB0, cB1, cB2, cB3, ah1[0], ah1[1], ah1[2], ah1[3], bl.z, bl.w);

            const int j0 = jch + nt * 8 + 2 * t4;
            float2 s2 = *(const float2*)&sqv[nt * 8 + 2 * t4];

            upd8(td0, ti0, (cA0 + cB0) + s2.x, j0);
            upd8(td0, ti0, (cA1 + cB1) + s2.y, j0 + 1);
            upd8(td1, ti1, (cA2 + cB2) + s2.x, j0);
            upd8(td1, ti1, (cA3 + cB3) + s2.y, j0 + 1);
        }
        __syncthreads();
    }

    // write partial lists: query rows q0+gid (list t4) and q0+gid+8
    {
        int base0 = ((q0 + gid) * NLIST + t4) * KNN;
        int base1 = ((q0 + gid + 8) * NLIST + t4) * KNN;
        #pragma unroll
        for (int k = 0; k < KNN; ++k) {
            g_pd[base0 + k] = td0[k];  g_pi[base0 + k] = ti0[k];
            g_pd[base1 + k] = td1[k];  g_pi[base1 + k] = ti1[k];
        }
    }
}

// ============================================================
// Kernel 3: merge NLIST partial top-8 lists -> final indices (lex order)
// ============================================================
__global__ void merge_kernel()
{
    int i = blockIdx.x * blockDim.x + threadIdx.x;
    if (i >= N) return;

    float d[NLIST * KNN];
    int   ix[NLIST * KNN];
    #pragma unroll
    for (int u = 0; u < NLIST * KNN; ++u) {
        d[u]  = g_pd[i * NLIST * KNN + u];
        ix[u] = g_pi[i * NLIST * KNN + u];
    }
    #pragma unroll
    for (int k = 0; k < KNN; ++k) {
        float bd = FLT_MAX; int bi = 0x7fffffff; int bu = 0;
        #pragma unroll
        for (int u = 0; u < NLIST * KNN; ++u) {
            if (d[u] < bd || (d[u] == bd && ix[u] < bi)) {
                bd = d[u]; bi = ix[u]; bu = u;
            }
        }
        g_idx[i * KNN + k] = bi;
        d[bu] = FLT_MAX; ix[bu] = 0x7fffffff;
    }
}

// ============================================================
// Kernel 4a: edge messages + mean (thread = (point, channel))
// ============================================================
__global__ void __launch_bounds__(256)
feats_kernel(const float* __restrict__ We, const float* __restrict__ be)
{
    __shared__ float sWd[16 * 16];
    __shared__ float sWb[16 * 16];
    __shared__ float sbe[16];
    __shared__ float sxi[16 * 16];
    __shared__ int   sj[16 * KNN];
    __shared__ float sxj[16 * KNN * 16];

    const int t  = threadIdx.x;
    const int i0 = blockIdx.x * 16;

    {
        float top = We[t];
        float bot = We[256 + t];
        sWd[t] = top - bot;
        sWb[t] = bot;
    }
    if (t < 16) sbe[t] = be[t];
    sxi[t] = g_x[i0 * 16 + t];
    if (t < 16 * KNN) sj[t] = g_idx[i0 * KNN + t];
    __syncthreads();

    {
        const float4* gx4 = (const float4*)g_x;
        float4* sxj4 = (float4*)sxj;
        #pragma unroll
        for (int u = t; u < 16 * KNN * 4; u += 256) {
            int row = u >> 2, seg = u & 3;
            sxj4[u] = gx4[sj[row] * 4 + seg];
        }
    }
    __syncthreads();

    const int p = t >> 4;
    const int h = t & 15;
    const int i = i0 + p;

    float pre = sbe[h];
    #pragma unroll
    for (int d = 0; d < 16; ++d) pre = fmaf(sxi[p * 16 + d], sWd[d * 16 + h], pre);

    float fsum = 0.0f;
    #pragma unroll
    for (int k = 0; k < KNN; ++k) {
        const float* xj = sxj + (p * KNN + k) * 16;
        float m = pre;
        #pragma unroll
        for (int d = 0; d < 16; ++d) m = fmaf(xj[d], sWb[d * 16 + h], m);
        fsum += silu_fast(m);
    }

    g_feats[i * 16 + h] = fsum * 0.125f;
}

// ============================================================
// Kernel 4b: final MLP + concat output
// ============================================================
__global__ void __launch_bounds__(256)
out_kernel(const float* __restrict__ xp,
           const float* __restrict__ Wf1, const float* __restrict__ bf1,
           const float* __restrict__ Wf2, const float* __restrict__ bf2,
           float* __restrict__ out)
{
    __shared__ float sWf1[16 * 32], sbf1[32];
    __shared__ float sWf2[32 * 16], sbf2[16];

    int t = threadIdx.x;
    for (int u = t; u < 16 * 32; u += 256) sWf1[u] = Wf1[u];
    for (int u = t; u < 32;      u += 256) sbf1[u] = bf1[u];
    for (int u = t; u < 32 * 16; u += 256) sWf2[u] = Wf2[u];
    for (int u = t; u < 16;      u += 256) sbf2[u] = bf2[u];
    __syncthreads();

    int i = blockIdx.x * 256 + t;
    if (i >= N) return;

    float feats[16];
    const float4* gf4 = (const float4*)g_feats;
    #pragma unroll
    for (int s = 0; s < 4; ++s) {
        float4 v = gf4[i * 4 + s];
        feats[4*s+0] = v.x; feats[4*s+1] = v.y; feats[4*s+2] = v.z; feats[4*s+3] = v.w;
    }

    float f1[32];
    #pragma unroll
    for (int h = 0; h < 32; ++h) {
        float a = sbf1[h];
        #pragma unroll
        for (int d = 0; d < 16; ++d) a = fmaf(feats[d], sWf1[d * 32 + h], a);
        f1[h] = silu_fast(a);
    }
    float f2[16];
    #pragma unroll
    for (int h = 0; h < 16; ++h) {
        float a = sbf2[h];
        #pragma unroll
        for (int d = 0; d < 32; ++d) a = fmaf(f1[d], sWf2[d * 16 + h], a);
        f2[h] = a;
    }

    float* o = out + i * (16 + DIN);
    #pragma unroll
    for (int h = 0; h < 16; ++h) o[h] = f2[h];
    #pragma unroll
    for (int d = 0; d < DIN; ++d) o[16 + d] = xp[i * DIN + d];
}

// ============================================================
extern "C" void kernel_launch(void* const* d_in, const int* in_sizes, int n_in,
                              void* d_out, int out_size)
{
    const float* xp  = (const float*)d_in[0];
    const float* W1  = (const float*)d_in[1];
    const float* b1  = (const float*)d_in[2];
    const float* W2  = (const float*)d_in[3];
    const float* b2  = (const float*)d_in[4];
    const float* W3  = (const float*)d_in[5];
    const float* b3  = (const float*)d_in[6];
    const float* We  = (const float*)d_in[7];
    const float* be  = (const float*)d_in[8];
    const float* Wf1 = (const float*)d_in[9];
    const float* bf1 = (const float*)d_in[10];
    const float* Wf2 = (const float*)d_in[11];
    const float* bf2 = (const float*)d_in[12];
    float* out = (float*)d_out;

    mlp_kernel<<<N / 256, 256>>>(xp, W1, b1, W2, b2, W3, b3);
    bfrag_kernel<<<(N / 8) * 32 / 256, 256>>>();
    knn_mma_kernel<<<N / QCTA, 128>>>();
    merge_kernel<<<N / 256, 256>>>();
    feats_kernel<<<N / 16, 256>>>(We, be);
    out_kernel<<<N / 256, 256>>>(xp, Wf1, bf1, Wf2, bf2, out);
}